// round 2
// baseline (speedup 1.0000x reference)
#include <cuda_runtime.h>
#include <math.h>

#define N_NODES 100000
#define E_EDGES 1600000
#define DD 128
#define NH 8
#define NDK 16
#define SCAN_BS 512
#define NB ((N_NODES + SCAN_BS - 1) / SCAN_BS)   // 196

// ---------------- scratch (device globals; no allocations) ----------------
__device__ float g_q [N_NODES * DD];        // [N][128]
__device__ float g_kv[N_NODES * 2 * DD];    // [N][256] : k' row then v' row per node
__device__ float g_t [N_NODES * DD];        // aggregated messages
__device__ float g_Weff[DD * 384];          // [k][j] transposed composed weights (q|k'|v')
__device__ float g_Wat [DD * DD];           // [k][j] transposed Wa
__device__ float g_beff[384];
__device__ int   g_cnt     [N_NODES];
__device__ int   g_rowstart[N_NODES];
__device__ int   g_cursor  [N_NODES];
__device__ int   g_csr_src [E_EDGES];
__device__ int   g_bsums   [256];

// ---------------- small helpers ----------------
__device__ __forceinline__ unsigned long long pack2(float x, float y) {
    unsigned long long r;
    asm("mov.b64 %0, {%1,%2};" : "=l"(r) : "f"(x), "f"(y));
    return r;
}
__device__ __forceinline__ float2 unpack2(unsigned long long v) {
    float2 f;
    asm("mov.b64 {%0,%1}, %2;" : "=f"(f.x), "=f"(f.y) : "l"(v));
    return f;
}
#define FMA2(c, a, b) asm("fma.rn.f32x2 %0, %1, %2, %0;" : "+l"(c) : "l"(a), "l"(b))

// ---------------- zero the histogram (no memset API needed) ----------------
__global__ void zero_cnt_kernel() {
    int i = blockIdx.x * blockDim.x + threadIdx.x;
    if (i < N_NODES) g_cnt[i] = 0;
}

// ---------------- K0: compose weights (fold rel_att/rel_msg into Wk/Wv), transpose ----------------
__global__ void build_weights(const float* __restrict__ Wk, const float* __restrict__ Wq,
                              const float* __restrict__ Wv, const float* __restrict__ Wa,
                              const float* __restrict__ rel_att, const float* __restrict__ rel_msg) {
    int idx = blockIdx.x * blockDim.x + threadIdx.x;   // 128 * 512 threads total
    int c = idx >> 9;
    int j = idx & 511;
    if (c >= DD) return;
    if (j < 128) {
        g_Weff[c * 384 + j] = Wq[j * DD + c];
    } else if (j < 384) {
        int jj = (j - 128) & 127;
        const float* W = (j < 256) ? Wk : Wv;
        const float* R = (j < 256) ? rel_att : rel_msg;
        int hh = jj >> 4, e = jj & 15;
        float s = 0.f;
#pragma unroll
        for (int d2 = 0; d2 < 16; d2++)
            s += W[(hh * 16 + d2) * DD + c] * R[hh * 256 + d2 * 16 + e];
        g_Weff[c * 384 + j] = s;
    } else {
        int jj = j - 384;
        g_Wat[c * DD + jj] = Wa[jj * DD + c];
    }
}

__global__ void build_bias(const float* __restrict__ bk, const float* __restrict__ bq,
                           const float* __restrict__ bv,
                           const float* __restrict__ rel_att, const float* __restrict__ rel_msg) {
    int j = threadIdx.x;   // 384 threads
    if (j >= 384) return;
    float val;
    if (j < 128) {
        val = bq[j];
    } else {
        int jj = (j - 128) & 127;
        const float* b = (j < 256) ? bk : bv;
        const float* R = (j < 256) ? rel_att : rel_msg;
        int hh = jj >> 4, e = jj & 15;
        float s = 0.f;
#pragma unroll
        for (int d2 = 0; d2 < 16; d2++)
            s += b[hh * 16 + d2] * R[hh * 256 + d2 * 16 + e];
        val = s;
    }
    g_beff[j] = val;
}

// ---------------- CSR build ----------------
__global__ void hist_kernel(const int* __restrict__ dst, int E) {
    int e = blockIdx.x * blockDim.x + threadIdx.x;
    if (e < E) atomicAdd(&g_cnt[dst[e]], 1);
}

__global__ void scan1_kernel() {
    __shared__ int sdata[SCAN_BS];
    int tid = threadIdx.x;
    int i = blockIdx.x * SCAN_BS + tid;
    int v = (i < N_NODES) ? g_cnt[i] : 0;
    sdata[tid] = v;
    __syncthreads();
#pragma unroll
    for (int off = 1; off < SCAN_BS; off <<= 1) {
        int x = (tid >= off) ? sdata[tid - off] : 0;
        __syncthreads();
        sdata[tid] += x;
        __syncthreads();
    }
    if (i < N_NODES) g_rowstart[i] = sdata[tid] - v;   // exclusive
    if (tid == SCAN_BS - 1) g_bsums[blockIdx.x] = sdata[tid];
}

__global__ void scan2_kernel() {
    __shared__ int sdata[256];
    int tid = threadIdx.x;
    int v = (tid < NB) ? g_bsums[tid] : 0;
    sdata[tid] = v;
    __syncthreads();
#pragma unroll
    for (int off = 1; off < 256; off <<= 1) {
        int x = (tid >= off) ? sdata[tid - off] : 0;
        __syncthreads();
        sdata[tid] += x;
        __syncthreads();
    }
    g_bsums[tid] = sdata[tid] - v;   // exclusive block offsets
}

__global__ void scan3_kernel() {
    int i = blockIdx.x * SCAN_BS + threadIdx.x;
    if (i < N_NODES) {
        int r = g_rowstart[i] + g_bsums[i >> 9];
        g_rowstart[i] = r;
        g_cursor[i] = r;
    }
}

__global__ void scatter_kernel(const int* __restrict__ src, const int* __restrict__ dst, int E) {
    int e = blockIdx.x * blockDim.x + threadIdx.x;
    if (e < E) {
        int p = atomicAdd(&g_cursor[dst[e]], 1);
        g_csr_src[p] = src[e];
    }
}

// ---------------- GEMM: C[n][j] = sum_k A[n][k] * Wt[k][j] (+epilogue) ----------------
// MODE 0: A = h, Wt = g_Weff (384 cols), +g_beff bias, writes g_q / g_kv
// MODE 1: A = g_t, Wt = g_Wat (128 cols), out = alpha*(acc+ba) + (1-alpha)*h
#define GEMM_SMEM ((128 * 132 + 128 * 128) * 4)

template <int MODE>
__global__ void __launch_bounds__(256, 1)
gemm128(const float* __restrict__ A, int nrows,
        const float* __restrict__ ba, const float* __restrict__ haux,
        const float* __restrict__ skip, float* __restrict__ outp) {
    extern __shared__ float sm[];
    float* As = sm;               // [128][132] row-major [m][k], padded
    float* Bs = sm + 128 * 132;   // [128][128] [k][j]

    const int tid = threadIdx.x;
    const int tx = tid & 15, ty = tid >> 4;
    const int m0 = blockIdx.x * 128;
    const int jb = blockIdx.y * 128;
    const float* Ap = (MODE == 0) ? A : g_t;
    const float* Wt = (MODE == 0) ? g_Weff : g_Wat;
    const int ldw = (MODE == 0) ? 384 : 128;

    // load A tile (coalesced float4 rows), zero-fill OOB rows
#pragma unroll
    for (int it = 0; it < 16; it++) {
        int idx = it * 256 + tid;
        int r = idx >> 5, c4 = idx & 31;
        int row = m0 + r;
        float4 val = make_float4(0.f, 0.f, 0.f, 0.f);
        if (row < nrows) val = *(const float4*)(Ap + row * DD + c4 * 4);
        *(float4*)(&As[r * 132 + c4 * 4]) = val;
    }
    // load B tile [k][j] directly from pre-transposed weights
#pragma unroll
    for (int it = 0; it < 16; it++) {
        int idx = it * 256 + tid;
        int k = idx >> 5, c4 = idx & 31;
        *(float4*)(&Bs[k * 128 + c4 * 4]) = *(const float4*)(Wt + k * ldw + jb + c4 * 4);
    }
    __syncthreads();

    unsigned long long acc[8][4];
#pragma unroll
    for (int i = 0; i < 8; i++)
#pragma unroll
        for (int p = 0; p < 4; p++) acc[i][p] = 0ull;

#pragma unroll 2
    for (int k4 = 0; k4 < 32; ++k4) {
        float4 a4[8];
#pragma unroll
        for (int i = 0; i < 8; ++i) {
            int rr = (i < 4) ? (ty * 4 + i) : (64 + ty * 4 + (i - 4));
            a4[i] = *(const float4*)(&As[rr * 132 + k4 * 4]);
        }
#pragma unroll
        for (int kk = 0; kk < 4; ++kk) {
            const float* brow = &Bs[(k4 * 4 + kk) * 128];
            float4 b0 = *(const float4*)(brow + tx * 4);
            float4 b1 = *(const float4*)(brow + 64 + tx * 4);
            unsigned long long bb0 = pack2(b0.x, b0.y);
            unsigned long long bb1 = pack2(b0.z, b0.w);
            unsigned long long bb2 = pack2(b1.x, b1.y);
            unsigned long long bb3 = pack2(b1.z, b1.w);
#pragma unroll
            for (int i = 0; i < 8; ++i) {
                float av = (kk == 0) ? a4[i].x : (kk == 1) ? a4[i].y : (kk == 2) ? a4[i].z : a4[i].w;
                unsigned long long aa = pack2(av, av);
                FMA2(acc[i][0], aa, bb0);
                FMA2(acc[i][1], aa, bb1);
                FMA2(acc[i][2], aa, bb2);
                FMA2(acc[i][3], aa, bb3);
            }
        }
    }

    // epilogue
    float alpha = 0.f, beta = 0.f;
    float4 e0, e1;
    if (MODE == 0) {
        e0 = *(const float4*)(g_beff + jb + tx * 4);
        e1 = *(const float4*)(g_beff + jb + 64 + tx * 4);
    } else {
        float s = __ldg(skip);
        alpha = 1.f / (1.f + __expf(-s));
        beta = 1.f - alpha;
        e0 = *(const float4*)(ba + tx * 4);
        e1 = *(const float4*)(ba + 64 + tx * 4);
    }

#pragma unroll
    for (int i = 0; i < 8; ++i) {
        int rr = (i < 4) ? (ty * 4 + i) : (64 + ty * 4 + (i - 4));
        int row = m0 + rr;
        if (row >= nrows) continue;
#pragma unroll
        for (int h2 = 0; h2 < 2; ++h2) {
            float2 p0 = unpack2(acc[i][h2 * 2]);
            float2 p1 = unpack2(acc[i][h2 * 2 + 1]);
            float4 o = make_float4(p0.x, p0.y, p1.x, p1.y);
            float4 bs = h2 ? e1 : e0;
            int jj = (h2 ? 64 : 0) + tx * 4;
            if (MODE == 0) {
                o.x += bs.x; o.y += bs.y; o.z += bs.z; o.w += bs.w;
                if (blockIdx.y == 0)
                    *(float4*)(g_q + row * DD + jj) = o;
                else
                    *(float4*)(g_kv + row * 2 * DD + (blockIdx.y - 1) * 128 + jj) = o;
            } else {
                float4 hv = *(const float4*)(haux + row * DD + jj);
                o.x = alpha * (o.x + bs.x) + beta * hv.x;
                o.y = alpha * (o.y + bs.y) + beta * hv.y;
                o.z = alpha * (o.z + bs.z) + beta * hv.z;
                o.w = alpha * (o.w + bs.w) + beta * hv.w;
                *(float4*)(outp + row * DD + jj) = o;
            }
        }
    }
}

// ---------------- fused edge softmax + aggregation: one warp per dst node ----------------
// t[d] = (sum_e exp(score_e) * v[src_e]) / (sum_e exp(score_e))   per head
// (max-subtraction dropped: scores ~N(0,1), exp safe in fp32; ratio unchanged)
__global__ void attn_kernel(const float* __restrict__ rel_pri) {
    int w = (blockIdx.x * blockDim.x + threadIdx.x) >> 5;
    int t = threadIdx.x & 31;
    if (w >= N_NODES) return;
    const int d = w;

    float4 q4 = *(const float4*)(g_q + d * DD + t * 4);
    float pri = __ldg(&rel_pri[t >> 2]) * 0.25f;   // rel_pri[h] / sqrt(DK)
    int start = g_rowstart[d];
    int cnt = g_cnt[d];

    float4 acc = make_float4(0.f, 0.f, 0.f, 0.f);
    float den = 0.f;
    const int* __restrict__ cs = g_csr_src + start;

    int s = (cnt > 0) ? cs[0] : 0;
    for (int i = 0; i < cnt; ++i) {
        int scur = s;
        if (i + 1 < cnt) s = cs[i + 1];
        const float4 k4 = *(const float4*)(g_kv + scur * 2 * DD + t * 4);
        const float4 v4 = *(const float4*)(g_kv + scur * 2 * DD + 128 + t * 4);
        float p = q4.x * k4.x + q4.y * k4.y + q4.z * k4.z + q4.w * k4.w;
        p += __shfl_xor_sync(0xffffffffu, p, 1);
        p += __shfl_xor_sync(0xffffffffu, p, 2);
        float ex = __expf(p * pri);
        den += ex;
        acc.x += ex * v4.x;
        acc.y += ex * v4.y;
        acc.z += ex * v4.z;
        acc.w += ex * v4.w;
    }
    float inv = (cnt > 0) ? (1.f / den) : 0.f;
    float4 o = make_float4(acc.x * inv, acc.y * inv, acc.z * inv, acc.w * inv);
    *(float4*)(g_t + d * DD + t * 4) = o;
}

// ---------------- launch ----------------
extern "C" void kernel_launch(void* const* d_in, const int* in_sizes, int n_in,
                              void* d_out, int out_size) {
    const float* h       = (const float*)d_in[0];
    const int*   src     = (const int*)d_in[1];
    const int*   dst     = (const int*)d_in[2];
    const float* Wk      = (const float*)d_in[3];
    const float* bk      = (const float*)d_in[4];
    const float* Wq      = (const float*)d_in[5];
    const float* bq      = (const float*)d_in[6];
    const float* Wv      = (const float*)d_in[7];
    const float* bv      = (const float*)d_in[8];
    const float* Wa      = (const float*)d_in[9];
    const float* ba      = (const float*)d_in[10];
    const float* rel_att = (const float*)d_in[11];
    const float* rel_msg = (const float*)d_in[12];
    const float* rel_pri = (const float*)d_in[13];
    const float* skip    = (const float*)d_in[14];

    const int n = in_sizes[0] / DD;   // 100000
    const int E = in_sizes[1];        // 1600000

    zero_cnt_kernel<<<(N_NODES + 255) / 256, 256>>>();

    build_weights<<<256, 256>>>(Wk, Wq, Wv, Wa, rel_att, rel_msg);
    build_bias<<<1, 384>>>(bk, bq, bv, rel_att, rel_msg);

    hist_kernel<<<(E + 255) / 256, 256>>>(dst, E);
    scan1_kernel<<<NB, SCAN_BS>>>();
    scan2_kernel<<<1, 256>>>();
    scan3_kernel<<<NB, SCAN_BS>>>();
    scatter_kernel<<<(E + 255) / 256, 256>>>(src, dst, E);

    cudaFuncSetAttribute(gemm128<0>, cudaFuncAttributeMaxDynamicSharedMemorySize, GEMM_SMEM);
    cudaFuncSetAttribute(gemm128<1>, cudaFuncAttributeMaxDynamicSharedMemorySize, GEMM_SMEM);

    gemm128<0><<<dim3((n + 127) / 128, 3), 256, GEMM_SMEM>>>(h, n, nullptr, nullptr, nullptr, nullptr);
    attn_kernel<<<(n + 7) / 8, 256>>>(rel_pri);
    gemm128<1><<<dim3((n + 127) / 128, 1), 256, GEMM_SMEM>>>(nullptr, n, ba, h, skip, (float*)d_out);
}

// round 3
// speedup vs baseline: 1.1293x; 1.1293x over previous
#include <cuda_runtime.h>
#include <cuda_fp16.h>
#include <math.h>

#define N_NODES 100000
#define E_EDGES 1600000
#define DD 128
#define NH 8
#define NDK 16
#define SCAN_BS 512
#define NB ((N_NODES + SCAN_BS - 1) / SCAN_BS)   // 196

// ---------------- scratch (device globals; no allocations) ----------------
__device__ float  g_q [N_NODES * DD];        // [N][128] fp32, rel_pri/sqrt_dk folded in
__device__ __half g_kv[N_NODES * 2 * DD];    // [N][256] halves: k' (128) then v' (128)
__device__ float  g_t [N_NODES * DD];        // aggregated messages
__device__ float  g_Weff[DD * 384];          // [k][j] transposed composed weights (q|k'|v')
__device__ float  g_Wat [DD * DD];           // [k][j] transposed Wa
__device__ float  g_beff[384];
__device__ int    g_cnt     [N_NODES];
__device__ int    g_rowstart[N_NODES];
__device__ int    g_cursor  [N_NODES];
__device__ int    g_csr_src [E_EDGES];
__device__ int    g_bsums   [256];

// ---------------- small helpers ----------------
__device__ __forceinline__ unsigned long long pack2(float x, float y) {
    unsigned long long r;
    asm("mov.b64 %0, {%1,%2};" : "=l"(r) : "f"(x), "f"(y));
    return r;
}
__device__ __forceinline__ float2 unpack2(unsigned long long v) {
    float2 f;
    asm("mov.b64 {%0,%1}, %2;" : "=f"(f.x), "=f"(f.y) : "l"(v));
    return f;
}
#define FMA2(c, a, b) asm("fma.rn.f32x2 %0, %1, %2, %0;" : "+l"(c) : "l"(a), "l"(b))

// ---------------- zero the histogram ----------------
__global__ void zero_cnt_kernel() {
    int i = blockIdx.x * blockDim.x + threadIdx.x;
    if (i < N_NODES) g_cnt[i] = 0;
}

// ---------------- compose weights (fold rel_att/rel_msg into Wk/Wv, rel_pri/sqrt_dk into Wq) ----------------
__global__ void build_weights(const float* __restrict__ Wk, const float* __restrict__ Wq,
                              const float* __restrict__ Wv, const float* __restrict__ Wa,
                              const float* __restrict__ rel_att, const float* __restrict__ rel_msg,
                              const float* __restrict__ rel_pri) {
    int idx = blockIdx.x * blockDim.x + threadIdx.x;   // 256*256 = 65536 threads
    int c = idx >> 9;
    int j = idx & 511;
    if (c >= DD) return;
    if (j < 128) {
        float pri = rel_pri[j >> 4] * 0.25f;           // rel_pri[h] / sqrt(DK)
        g_Weff[c * 384 + j] = Wq[j * DD + c] * pri;
    } else if (j < 384) {
        int jj = (j - 128) & 127;
        const float* W = (j < 256) ? Wk : Wv;
        const float* R = (j < 256) ? rel_att : rel_msg;
        int hh = jj >> 4, e = jj & 15;
        float s = 0.f;
#pragma unroll
        for (int d2 = 0; d2 < 16; d2++)
            s += W[(hh * 16 + d2) * DD + c] * R[hh * 256 + d2 * 16 + e];
        g_Weff[c * 384 + j] = s;
    } else {
        int jj = j - 384;
        g_Wat[c * DD + jj] = Wa[jj * DD + c];
    }
}

__global__ void build_bias(const float* __restrict__ bk, const float* __restrict__ bq,
                           const float* __restrict__ bv,
                           const float* __restrict__ rel_att, const float* __restrict__ rel_msg,
                           const float* __restrict__ rel_pri) {
    int j = threadIdx.x;   // 384 threads
    if (j >= 384) return;
    float val;
    if (j < 128) {
        val = bq[j] * rel_pri[j >> 4] * 0.25f;
    } else {
        int jj = (j - 128) & 127;
        const float* b = (j < 256) ? bk : bv;
        const float* R = (j < 256) ? rel_att : rel_msg;
        int hh = jj >> 4, e = jj & 15;
        float s = 0.f;
#pragma unroll
        for (int d2 = 0; d2 < 16; d2++)
            s += b[hh * 16 + d2] * R[hh * 256 + d2 * 16 + e];
        val = s;
    }
    g_beff[j] = val;
}

// ---------------- CSR build ----------------
__global__ void hist_kernel(const int* __restrict__ dst, int E) {
    int e = blockIdx.x * blockDim.x + threadIdx.x;
    if (e < E) atomicAdd(&g_cnt[dst[e]], 1);
}

__global__ void scan1_kernel() {
    __shared__ int sdata[SCAN_BS];
    int tid = threadIdx.x;
    int i = blockIdx.x * SCAN_BS + tid;
    int v = (i < N_NODES) ? g_cnt[i] : 0;
    sdata[tid] = v;
    __syncthreads();
#pragma unroll
    for (int off = 1; off < SCAN_BS; off <<= 1) {
        int x = (tid >= off) ? sdata[tid - off] : 0;
        __syncthreads();
        sdata[tid] += x;
        __syncthreads();
    }
    if (i < N_NODES) g_rowstart[i] = sdata[tid] - v;   // exclusive
    if (tid == SCAN_BS - 1) g_bsums[blockIdx.x] = sdata[tid];
}

__global__ void scan2_kernel() {
    __shared__ int sdata[256];
    int tid = threadIdx.x;
    int v = (tid < NB) ? g_bsums[tid] : 0;
    sdata[tid] = v;
    __syncthreads();
#pragma unroll
    for (int off = 1; off < 256; off <<= 1) {
        int x = (tid >= off) ? sdata[tid - off] : 0;
        __syncthreads();
        sdata[tid] += x;
        __syncthreads();
    }
    g_bsums[tid] = sdata[tid] - v;   // exclusive block offsets
}

__global__ void scan3_kernel() {
    int i = blockIdx.x * SCAN_BS + threadIdx.x;
    if (i < N_NODES) {
        int r = g_rowstart[i] + g_bsums[i >> 9];
        g_rowstart[i] = r;
        g_cursor[i] = r;
    }
}

__global__ void scatter_kernel(const int* __restrict__ src, const int* __restrict__ dst, int E) {
    int e = blockIdx.x * blockDim.x + threadIdx.x;
    if (e < E) {
        int p = atomicAdd(&g_cursor[dst[e]], 1);
        g_csr_src[p] = src[e];
    }
}

// ---------------- GEMM: C[n][j] = sum_k A[n][k] * Wt[k][j] (+epilogue) ----------------
// MODE 0: A = h, Wt = g_Weff (384 cols), +g_beff bias; y=0 -> g_q fp32, y=1/2 -> g_kv fp16
// MODE 1: A = g_t, Wt = g_Wat (128 cols), out = alpha*(acc+ba) + (1-alpha)*h
#define GEMM_SMEM ((128 * 132 + 128 * 128) * 4)

template <int MODE>
__global__ void __launch_bounds__(256, 1)
gemm128(const float* __restrict__ A, int nrows,
        const float* __restrict__ ba, const float* __restrict__ haux,
        const float* __restrict__ skip, float* __restrict__ outp) {
    extern __shared__ float sm[];
    float* As = sm;               // [128][132]
    float* Bs = sm + 128 * 132;   // [128][128]

    const int tid = threadIdx.x;
    const int tx = tid & 15, ty = tid >> 4;
    const int m0 = blockIdx.x * 128;
    const int jb = blockIdx.y * 128;
    const float* Ap = (MODE == 0) ? A : g_t;
    const float* Wt = (MODE == 0) ? g_Weff : g_Wat;
    const int ldw = (MODE == 0) ? 384 : 128;

#pragma unroll
    for (int it = 0; it < 16; it++) {
        int idx = it * 256 + tid;
        int r = idx >> 5, c4 = idx & 31;
        int row = m0 + r;
        float4 val = make_float4(0.f, 0.f, 0.f, 0.f);
        if (row < nrows) val = *(const float4*)(Ap + row * DD + c4 * 4);
        *(float4*)(&As[r * 132 + c4 * 4]) = val;
    }
#pragma unroll
    for (int it = 0; it < 16; it++) {
        int idx = it * 256 + tid;
        int k = idx >> 5, c4 = idx & 31;
        *(float4*)(&Bs[k * 128 + c4 * 4]) = *(const float4*)(Wt + k * ldw + jb + c4 * 4);
    }
    __syncthreads();

    unsigned long long acc[8][4];
#pragma unroll
    for (int i = 0; i < 8; i++)
#pragma unroll
        for (int p = 0; p < 4; p++) acc[i][p] = 0ull;

#pragma unroll 2
    for (int k4 = 0; k4 < 32; ++k4) {
        float4 a4[8];
#pragma unroll
        for (int i = 0; i < 8; ++i) {
            int rr = (i < 4) ? (ty * 4 + i) : (64 + ty * 4 + (i - 4));
            a4[i] = *(const float4*)(&As[rr * 132 + k4 * 4]);
        }
#pragma unroll
        for (int kk = 0; kk < 4; ++kk) {
            const float* brow = &Bs[(k4 * 4 + kk) * 128];
            float4 b0 = *(const float4*)(brow + tx * 4);
            float4 b1 = *(const float4*)(brow + 64 + tx * 4);
            unsigned long long bb0 = pack2(b0.x, b0.y);
            unsigned long long bb1 = pack2(b0.z, b0.w);
            unsigned long long bb2 = pack2(b1.x, b1.y);
            unsigned long long bb3 = pack2(b1.z, b1.w);
#pragma unroll
            for (int i = 0; i < 8; ++i) {
                float av = (kk == 0) ? a4[i].x : (kk == 1) ? a4[i].y : (kk == 2) ? a4[i].z : a4[i].w;
                unsigned long long aa = pack2(av, av);
                FMA2(acc[i][0], aa, bb0);
                FMA2(acc[i][1], aa, bb1);
                FMA2(acc[i][2], aa, bb2);
                FMA2(acc[i][3], aa, bb3);
            }
        }
    }

    // epilogue
    float alpha = 0.f, beta = 0.f;
    float4 e0, e1;
    if (MODE == 0) {
        e0 = *(const float4*)(g_beff + jb + tx * 4);
        e1 = *(const float4*)(g_beff + jb + 64 + tx * 4);
    } else {
        float s = __ldg(skip);
        alpha = 1.f / (1.f + __expf(-s));
        beta = 1.f - alpha;
        e0 = *(const float4*)(ba + tx * 4);
        e1 = *(const float4*)(ba + 64 + tx * 4);
    }

#pragma unroll
    for (int i = 0; i < 8; ++i) {
        int rr = (i < 4) ? (ty * 4 + i) : (64 + ty * 4 + (i - 4));
        int row = m0 + rr;
        if (row >= nrows) continue;
#pragma unroll
        for (int h2 = 0; h2 < 2; ++h2) {
            float2 p0 = unpack2(acc[i][h2 * 2]);
            float2 p1 = unpack2(acc[i][h2 * 2 + 1]);
            float4 o = make_float4(p0.x, p0.y, p1.x, p1.y);
            float4 bs = h2 ? e1 : e0;
            int jj = (h2 ? 64 : 0) + tx * 4;
            if (MODE == 0) {
                o.x += bs.x; o.y += bs.y; o.z += bs.z; o.w += bs.w;
                if (blockIdx.y == 0) {
                    *(float4*)(g_q + row * DD + jj) = o;
                } else {
                    __half2 p01 = __floats2half2_rn(o.x, o.y);
                    __half2 p23 = __floats2half2_rn(o.z, o.w);
                    uint2 u;
                    u.x = *reinterpret_cast<unsigned*>(&p01);
                    u.y = *reinterpret_cast<unsigned*>(&p23);
                    *reinterpret_cast<uint2*>(g_kv + row * 2 * DD + (blockIdx.y - 1) * 128 + jj) = u;
                }
            } else {
                float4 hv = *(const float4*)(haux + row * DD + jj);
                o.x = alpha * (o.x + bs.x) + beta * hv.x;
                o.y = alpha * (o.y + bs.y) + beta * hv.y;
                o.z = alpha * (o.z + bs.z) + beta * hv.z;
                o.w = alpha * (o.w + bs.w) + beta * hv.w;
                *(float4*)(outp + row * DD + jj) = o;
            }
        }
    }
}

// ---------------- fused edge softmax + aggregation: one warp per dst node ----------------
// k'/v' in fp16 (512B per edge instead of 1KB); q pre-scaled by rel_pri/sqrt_dk.
__global__ void attn_kernel() {
    int w = (blockIdx.x * blockDim.x + threadIdx.x) >> 5;
    int t = threadIdx.x & 31;
    if (w >= N_NODES) return;
    const int d = w;

    float4 q4 = *(const float4*)(g_q + d * DD + t * 4);
    int start = g_rowstart[d];
    int cnt = g_cnt[d];

    float4 acc = make_float4(0.f, 0.f, 0.f, 0.f);
    float den = 0.f;
    const int* __restrict__ cs = g_csr_src + start;

    int s = (cnt > 0) ? cs[0] : 0;
    for (int i = 0; i < cnt; ++i) {
        int scur = s;
        if (i + 1 < cnt) s = cs[i + 1];
        const uint2* __restrict__ rowp = reinterpret_cast<const uint2*>(g_kv + scur * 2 * DD);
        uint2 ku = rowp[t];        // 4 halves of k'
        uint2 vu = rowp[32 + t];   // 4 halves of v'
        float2 k01 = __half22float2(*reinterpret_cast<__half2*>(&ku.x));
        float2 k23 = __half22float2(*reinterpret_cast<__half2*>(&ku.y));
        float p = q4.x * k01.x + q4.y * k01.y + q4.z * k23.x + q4.w * k23.y;
        p += __shfl_xor_sync(0xffffffffu, p, 1);
        p += __shfl_xor_sync(0xffffffffu, p, 2);
        float ex = __expf(p);
        float2 v01 = __half22float2(*reinterpret_cast<__half2*>(&vu.x));
        float2 v23 = __half22float2(*reinterpret_cast<__half2*>(&vu.y));
        den += ex;
        acc.x += ex * v01.x;
        acc.y += ex * v01.y;
        acc.z += ex * v23.x;
        acc.w += ex * v23.y;
    }
    float inv = (cnt > 0) ? (1.f / den) : 0.f;
    float4 o = make_float4(acc.x * inv, acc.y * inv, acc.z * inv, acc.w * inv);
    *(float4*)(g_t + d * DD + t * 4) = o;
}

// ---------------- launch ----------------
extern "C" void kernel_launch(void* const* d_in, const int* in_sizes, int n_in,
                              void* d_out, int out_size) {
    const float* h       = (const float*)d_in[0];
    const int*   src     = (const int*)d_in[1];
    const int*   dst     = (const int*)d_in[2];
    const float* Wk      = (const float*)d_in[3];
    const float* bk      = (const float*)d_in[4];
    const float* Wq      = (const float*)d_in[5];
    const float* bq      = (const float*)d_in[6];
    const float* Wv      = (const float*)d_in[7];
    const float* bv      = (const float*)d_in[8];
    const float* Wa      = (const float*)d_in[9];
    const float* ba      = (const float*)d_in[10];
    const float* rel_att = (const float*)d_in[11];
    const float* rel_msg = (const float*)d_in[12];
    const float* rel_pri = (const float*)d_in[13];
    const float* skip    = (const float*)d_in[14];

    const int n = in_sizes[0] / DD;   // 100000
    const int E = in_sizes[1];        // 1600000

    zero_cnt_kernel<<<(N_NODES + 255) / 256, 256>>>();

    build_weights<<<256, 256>>>(Wk, Wq, Wv, Wa, rel_att, rel_msg, rel_pri);
    build_bias<<<1, 384>>>(bk, bq, bv, rel_att, rel_msg, rel_pri);

    hist_kernel<<<(E + 255) / 256, 256>>>(dst, E);
    scan1_kernel<<<NB, SCAN_BS>>>();
    scan2_kernel<<<1, 256>>>();
    scan3_kernel<<<NB, SCAN_BS>>>();
    scatter_kernel<<<(E + 255) / 256, 256>>>(src, dst, E);

    cudaFuncSetAttribute(gemm128<0>, cudaFuncAttributeMaxDynamicSharedMemorySize, GEMM_SMEM);
    cudaFuncSetAttribute(gemm128<1>, cudaFuncAttributeMaxDynamicSharedMemorySize, GEMM_SMEM);

    gemm128<0><<<dim3((n + 127) / 128, 3), 256, GEMM_SMEM>>>(h, n, nullptr, nullptr, nullptr, nullptr);
    attn_kernel<<<(n * 32 + 255) / 256, 256>>>();
    gemm128<1><<<dim3((n + 127) / 128, 1), 256, GEMM_SMEM>>>(nullptr, n, ba, h, skip, (float*)d_out);
}

// round 4
// speedup vs baseline: 1.2295x; 1.0887x over previous
#include <cuda_runtime.h>
#include <cuda_fp16.h>
#include <math.h>

#define N_NODES 100000
#define E_EDGES 1600000
#define DD 128
#define NH 8
#define NDK 16
#define SCAN_BS 512
#define NB ((N_NODES + SCAN_BS - 1) / SCAN_BS)   // 196

// ---------------- scratch (device globals; no allocations) ----------------
__device__ float  g_q [N_NODES * DD];        // [N][128] fp32, rel_pri/sqrt_dk folded in
__device__ __half g_kv[N_NODES * 2 * DD];    // [N][256] halves: k' (128) then v' (128)
__device__ float  g_t [N_NODES * DD];        // aggregated messages
__device__ float  g_Weff[DD * 384];          // [k][j] transposed composed weights (q|k'|v')
__device__ float  g_Wat [DD * DD];           // [k][j] transposed Wa
__device__ float  g_beff[384];
__device__ int    g_cnt     [N_NODES];
__device__ int    g_rowstart[N_NODES];
__device__ int    g_cursor  [N_NODES];
__device__ int    g_csr_src [E_EDGES];
__device__ int    g_bsums   [256];

// ---------------- small helpers ----------------
__device__ __forceinline__ unsigned long long pack2(float x, float y) {
    unsigned long long r;
    asm("mov.b64 %0, {%1,%2};" : "=l"(r) : "f"(x), "f"(y));
    return r;
}
__device__ __forceinline__ float2 unpack2(unsigned long long v) {
    float2 f;
    asm("mov.b64 {%0,%1}, %2;" : "=f"(f.x), "=f"(f.y) : "l"(v));
    return f;
}
#define FMA2(c, a, b) asm("fma.rn.f32x2 %0, %1, %2, %0;" : "+l"(c) : "l"(a), "l"(b))

// ---------------- zero the histogram ----------------
__global__ void zero_cnt_kernel() {
    int i = blockIdx.x * blockDim.x + threadIdx.x;
    if (i < N_NODES) g_cnt[i] = 0;
}

// ---------------- compose weights ----------------
__global__ void build_weights(const float* __restrict__ Wk, const float* __restrict__ Wq,
                              const float* __restrict__ Wv, const float* __restrict__ Wa,
                              const float* __restrict__ rel_att, const float* __restrict__ rel_msg,
                              const float* __restrict__ rel_pri) {
    int idx = blockIdx.x * blockDim.x + threadIdx.x;   // 65536 threads
    int c = idx >> 9;
    int j = idx & 511;
    if (c >= DD) return;
    if (j < 128) {
        float pri = rel_pri[j >> 4] * 0.25f;           // rel_pri[h] / sqrt(DK)
        g_Weff[c * 384 + j] = Wq[j * DD + c] * pri;
    } else if (j < 384) {
        int jj = (j - 128) & 127;
        const float* W = (j < 256) ? Wk : Wv;
        const float* R = (j < 256) ? rel_att : rel_msg;
        int hh = jj >> 4, e = jj & 15;
        float s = 0.f;
#pragma unroll
        for (int d2 = 0; d2 < 16; d2++)
            s += W[(hh * 16 + d2) * DD + c] * R[hh * 256 + d2 * 16 + e];
        g_Weff[c * 384 + j] = s;
    } else {
        int jj = j - 384;
        g_Wat[c * DD + jj] = Wa[jj * DD + c];
    }
}

__global__ void build_bias(const float* __restrict__ bk, const float* __restrict__ bq,
                           const float* __restrict__ bv,
                           const float* __restrict__ rel_att, const float* __restrict__ rel_msg,
                           const float* __restrict__ rel_pri) {
    int j = threadIdx.x;   // 384 threads
    if (j >= 384) return;
    float val;
    if (j < 128) {
        val = bq[j] * rel_pri[j >> 4] * 0.25f;
    } else {
        int jj = (j - 128) & 127;
        const float* b = (j < 256) ? bk : bv;
        const float* R = (j < 256) ? rel_att : rel_msg;
        int hh = jj >> 4, e = jj & 15;
        float s = 0.f;
#pragma unroll
        for (int d2 = 0; d2 < 16; d2++)
            s += b[hh * 16 + d2] * R[hh * 256 + d2 * 16 + e];
        val = s;
    }
    g_beff[j] = val;
}

// ---------------- CSR build ----------------
__global__ void hist_kernel(const int* __restrict__ dst, int E) {
    int e = blockIdx.x * blockDim.x + threadIdx.x;
    if (e < E) atomicAdd(&g_cnt[dst[e]], 1);
}

__global__ void scan1_kernel() {
    __shared__ int sdata[SCAN_BS];
    int tid = threadIdx.x;
    int i = blockIdx.x * SCAN_BS + tid;
    int v = (i < N_NODES) ? g_cnt[i] : 0;
    sdata[tid] = v;
    __syncthreads();
#pragma unroll
    for (int off = 1; off < SCAN_BS; off <<= 1) {
        int x = (tid >= off) ? sdata[tid - off] : 0;
        __syncthreads();
        sdata[tid] += x;
        __syncthreads();
    }
    if (i < N_NODES) g_rowstart[i] = sdata[tid] - v;   // exclusive
    if (tid == SCAN_BS - 1) g_bsums[blockIdx.x] = sdata[tid];
}

__global__ void scan2_kernel() {
    __shared__ int sdata[256];
    int tid = threadIdx.x;
    int v = (tid < NB) ? g_bsums[tid] : 0;
    sdata[tid] = v;
    __syncthreads();
#pragma unroll
    for (int off = 1; off < 256; off <<= 1) {
        int x = (tid >= off) ? sdata[tid - off] : 0;
        __syncthreads();
        sdata[tid] += x;
        __syncthreads();
    }
    g_bsums[tid] = sdata[tid] - v;   // exclusive block offsets
}

__global__ void scan3_kernel() {
    int i = blockIdx.x * SCAN_BS + threadIdx.x;
    if (i < N_NODES) {
        int r = g_rowstart[i] + g_bsums[i >> 9];
        g_rowstart[i] = r;
        g_cursor[i] = r;
    }
}

__global__ void scatter_kernel(const int* __restrict__ src, const int* __restrict__ dst, int E) {
    int e = blockIdx.x * blockDim.x + threadIdx.x;
    if (e < E) {
        int p = atomicAdd(&g_cursor[dst[e]], 1);
        g_csr_src[p] = src[e];
    }
}

// ---------------- GEMM: C[n][j] = sum_k A[n][k] * Wt[k][j] (+epilogue) ----------------
#define GEMM_SMEM ((128 * 132 + 128 * 128) * 4)

template <int MODE>
__global__ void __launch_bounds__(256, 1)
gemm128(const float* __restrict__ A, int nrows,
        const float* __restrict__ ba, const float* __restrict__ haux,
        const float* __restrict__ skip, float* __restrict__ outp) {
    extern __shared__ float sm[];
    float* As = sm;               // [128][132]
    float* Bs = sm + 128 * 132;   // [128][128]

    const int tid = threadIdx.x;
    const int tx = tid & 15, ty = tid >> 4;
    const int m0 = blockIdx.x * 128;
    const int jb = blockIdx.y * 128;
    const float* Ap = (MODE == 0) ? A : g_t;
    const float* Wt = (MODE == 0) ? g_Weff : g_Wat;
    const int ldw = (MODE == 0) ? 384 : 128;

#pragma unroll
    for (int it = 0; it < 16; it++) {
        int idx = it * 256 + tid;
        int r = idx >> 5, c4 = idx & 31;
        int row = m0 + r;
        float4 val = make_float4(0.f, 0.f, 0.f, 0.f);
        if (row < nrows) val = *(const float4*)(Ap + row * DD + c4 * 4);
        *(float4*)(&As[r * 132 + c4 * 4]) = val;
    }
#pragma unroll
    for (int it = 0; it < 16; it++) {
        int idx = it * 256 + tid;
        int k = idx >> 5, c4 = idx & 31;
        *(float4*)(&Bs[k * 128 + c4 * 4]) = *(const float4*)(Wt + k * ldw + jb + c4 * 4);
    }
    __syncthreads();

    unsigned long long acc[8][4];
#pragma unroll
    for (int i = 0; i < 8; i++)
#pragma unroll
        for (int p = 0; p < 4; p++) acc[i][p] = 0ull;

#pragma unroll 2
    for (int k4 = 0; k4 < 32; ++k4) {
        float4 a4[8];
#pragma unroll
        for (int i = 0; i < 8; ++i) {
            int rr = (i < 4) ? (ty * 4 + i) : (64 + ty * 4 + (i - 4));
            a4[i] = *(const float4*)(&As[rr * 132 + k4 * 4]);
        }
#pragma unroll
        for (int kk = 0; kk < 4; ++kk) {
            const float* brow = &Bs[(k4 * 4 + kk) * 128];
            float4 b0 = *(const float4*)(brow + tx * 4);
            float4 b1 = *(const float4*)(brow + 64 + tx * 4);
            unsigned long long bb0 = pack2(b0.x, b0.y);
            unsigned long long bb1 = pack2(b0.z, b0.w);
            unsigned long long bb2 = pack2(b1.x, b1.y);
            unsigned long long bb3 = pack2(b1.z, b1.w);
#pragma unroll
            for (int i = 0; i < 8; ++i) {
                float av = (kk == 0) ? a4[i].x : (kk == 1) ? a4[i].y : (kk == 2) ? a4[i].z : a4[i].w;
                unsigned long long aa = pack2(av, av);
                FMA2(acc[i][0], aa, bb0);
                FMA2(acc[i][1], aa, bb1);
                FMA2(acc[i][2], aa, bb2);
                FMA2(acc[i][3], aa, bb3);
            }
        }
    }

    // epilogue
    float alpha = 0.f, beta = 0.f;
    float4 e0, e1;
    if (MODE == 0) {
        e0 = *(const float4*)(g_beff + jb + tx * 4);
        e1 = *(const float4*)(g_beff + jb + 64 + tx * 4);
    } else {
        float s = __ldg(skip);
        alpha = 1.f / (1.f + __expf(-s));
        beta = 1.f - alpha;
        e0 = *(const float4*)(ba + tx * 4);
        e1 = *(const float4*)(ba + 64 + tx * 4);
    }

#pragma unroll
    for (int i = 0; i < 8; ++i) {
        int rr = (i < 4) ? (ty * 4 + i) : (64 + ty * 4 + (i - 4));
        int row = m0 + rr;
        if (row >= nrows) continue;
#pragma unroll
        for (int h2 = 0; h2 < 2; ++h2) {
            float2 p0 = unpack2(acc[i][h2 * 2]);
            float2 p1 = unpack2(acc[i][h2 * 2 + 1]);
            float4 o = make_float4(p0.x, p0.y, p1.x, p1.y);
            float4 bs = h2 ? e1 : e0;
            int jj = (h2 ? 64 : 0) + tx * 4;
            if (MODE == 0) {
                o.x += bs.x; o.y += bs.y; o.z += bs.z; o.w += bs.w;
                if (blockIdx.y == 0) {
                    *(float4*)(g_q + row * DD + jj) = o;
                } else {
                    __half2 p01 = __floats2half2_rn(o.x, o.y);
                    __half2 p23 = __floats2half2_rn(o.z, o.w);
                    uint2 u;
                    u.x = *reinterpret_cast<unsigned*>(&p01);
                    u.y = *reinterpret_cast<unsigned*>(&p23);
                    *reinterpret_cast<uint2*>(g_kv + row * 2 * DD + (blockIdx.y - 1) * 128 + jj) = u;
                }
            } else {
                float4 hv = *(const float4*)(haux + row * DD + jj);
                o.x = alpha * (o.x + bs.x) + beta * hv.x;
                o.y = alpha * (o.y + bs.y) + beta * hv.y;
                o.z = alpha * (o.z + bs.z) + beta * hv.z;
                o.w = alpha * (o.w + bs.w) + beta * hv.w;
                *(float4*)(outp + row * DD + jj) = o;
            }
        }
    }
}

// ---------------- fused edge softmax + aggregation: one warp per dst node ----------------
// 2x unrolled edge loop: two independent k/v load pairs per iteration for MLP.
__global__ void attn_kernel() {
    int w = (blockIdx.x * blockDim.x + threadIdx.x) >> 5;
    int t = threadIdx.x & 31;
    if (w >= N_NODES) return;
    const int d = w;

    float4 q4 = *(const float4*)(g_q + d * DD + t * 4);
    int start = g_rowstart[d];
    int cnt = g_cnt[d];

    float4 acc = make_float4(0.f, 0.f, 0.f, 0.f);
    float den = 0.f;
    const int* __restrict__ cs = g_csr_src + start;

    int i = 0;
    for (; i + 2 <= cnt; i += 2) {
        int s0 = cs[i];
        int s1 = cs[i + 1];
        const uint2* __restrict__ r0 = reinterpret_cast<const uint2*>(g_kv + s0 * 2 * DD);
        const uint2* __restrict__ r1 = reinterpret_cast<const uint2*>(g_kv + s1 * 2 * DD);
        uint2 ku0 = r0[t];
        uint2 vu0 = r0[32 + t];
        uint2 ku1 = r1[t];
        uint2 vu1 = r1[32 + t];

        float2 k01 = __half22float2(*reinterpret_cast<__half2*>(&ku0.x));
        float2 k23 = __half22float2(*reinterpret_cast<__half2*>(&ku0.y));
        float p0 = q4.x * k01.x + q4.y * k01.y + q4.z * k23.x + q4.w * k23.y;
        float2 m01 = __half22float2(*reinterpret_cast<__half2*>(&ku1.x));
        float2 m23 = __half22float2(*reinterpret_cast<__half2*>(&ku1.y));
        float p1 = q4.x * m01.x + q4.y * m01.y + q4.z * m23.x + q4.w * m23.y;

        p0 += __shfl_xor_sync(0xffffffffu, p0, 1);
        p1 += __shfl_xor_sync(0xffffffffu, p1, 1);
        p0 += __shfl_xor_sync(0xffffffffu, p0, 2);
        p1 += __shfl_xor_sync(0xffffffffu, p1, 2);
        float ex0 = __expf(p0);
        float ex1 = __expf(p1);

        float2 v01 = __half22float2(*reinterpret_cast<__half2*>(&vu0.x));
        float2 v23 = __half22float2(*reinterpret_cast<__half2*>(&vu0.y));
        float2 w01 = __half22float2(*reinterpret_cast<__half2*>(&vu1.x));
        float2 w23 = __half22float2(*reinterpret_cast<__half2*>(&vu1.y));
        den += ex0 + ex1;
        acc.x += ex0 * v01.x + ex1 * w01.x;
        acc.y += ex0 * v01.y + ex1 * w01.y;
        acc.z += ex0 * v23.x + ex1 * w23.x;
        acc.w += ex0 * v23.y + ex1 * w23.y;
    }
    if (i < cnt) {
        int s0 = cs[i];
        const uint2* __restrict__ r0 = reinterpret_cast<const uint2*>(g_kv + s0 * 2 * DD);
        uint2 ku0 = r0[t];
        uint2 vu0 = r0[32 + t];
        float2 k01 = __half22float2(*reinterpret_cast<__half2*>(&ku0.x));
        float2 k23 = __half22float2(*reinterpret_cast<__half2*>(&ku0.y));
        float p0 = q4.x * k01.x + q4.y * k01.y + q4.z * k23.x + q4.w * k23.y;
        p0 += __shfl_xor_sync(0xffffffffu, p0, 1);
        p0 += __shfl_xor_sync(0xffffffffu, p0, 2);
        float ex0 = __expf(p0);
        float2 v01 = __half22float2(*reinterpret_cast<__half2*>(&vu0.x));
        float2 v23 = __half22float2(*reinterpret_cast<__half2*>(&vu0.y));
        den += ex0;
        acc.x += ex0 * v01.x;
        acc.y += ex0 * v01.y;
        acc.z += ex0 * v23.x;
        acc.w += ex0 * v23.y;
    }
    float inv = (cnt > 0) ? (1.f / den) : 0.f;
    float4 o = make_float4(acc.x * inv, acc.y * inv, acc.z * inv, acc.w * inv);
    *(float4*)(g_t + d * DD + t * 4) = o;
}

// ---------------- launch: CSR chain forked onto a side stream ----------------
extern "C" void kernel_launch(void* const* d_in, const int* in_sizes, int n_in,
                              void* d_out, int out_size) {
    const float* h       = (const float*)d_in[0];
    const int*   src     = (const int*)d_in[1];
    const int*   dst     = (const int*)d_in[2];
    const float* Wk      = (const float*)d_in[3];
    const float* bk      = (const float*)d_in[4];
    const float* Wq      = (const float*)d_in[5];
    const float* bq      = (const float*)d_in[6];
    const float* Wv      = (const float*)d_in[7];
    const float* bv      = (const float*)d_in[8];
    const float* Wa      = (const float*)d_in[9];
    const float* ba      = (const float*)d_in[10];
    const float* rel_att = (const float*)d_in[11];
    const float* rel_msg = (const float*)d_in[12];
    const float* rel_pri = (const float*)d_in[13];
    const float* skip    = (const float*)d_in[14];

    const int n = in_sizes[0] / DD;   // 100000
    const int E = in_sizes[1];        // 1600000

    // one-time host-side objects (no device memory involved)
    static cudaStream_t s2 = nullptr;
    static cudaEvent_t ev_fork = nullptr, ev_join = nullptr;
    static bool attr_done = false;
    if (!s2) {
        cudaStreamCreateWithFlags(&s2, cudaStreamNonBlocking);
        cudaEventCreateWithFlags(&ev_fork, cudaEventDisableTiming);
        cudaEventCreateWithFlags(&ev_join, cudaEventDisableTiming);
    }
    if (!attr_done) {
        cudaFuncSetAttribute(gemm128<0>, cudaFuncAttributeMaxDynamicSharedMemorySize, GEMM_SMEM);
        cudaFuncSetAttribute(gemm128<1>, cudaFuncAttributeMaxDynamicSharedMemorySize, GEMM_SMEM);
        attr_done = true;
    }

    // fork: CSR chain on s2, projection chain on the main (capture) stream
    cudaEventRecord(ev_fork, 0);
    cudaStreamWaitEvent(s2, ev_fork, 0);

    zero_cnt_kernel<<<(N_NODES + 255) / 256, 256, 0, s2>>>();
    hist_kernel<<<(E + 255) / 256, 256, 0, s2>>>(dst, E);
    scan1_kernel<<<NB, SCAN_BS, 0, s2>>>();
    scan2_kernel<<<1, 256, 0, s2>>>();
    scan3_kernel<<<NB, SCAN_BS, 0, s2>>>();
    scatter_kernel<<<(E + 255) / 256, 256, 0, s2>>>(src, dst, E);
    cudaEventRecord(ev_join, s2);

    build_weights<<<256, 256>>>(Wk, Wq, Wv, Wa, rel_att, rel_msg, rel_pri);
    build_bias<<<1, 384>>>(bk, bq, bv, rel_att, rel_msg, rel_pri);
    gemm128<0><<<dim3((n + 127) / 128, 3), 256, GEMM_SMEM>>>(h, n, nullptr, nullptr, nullptr, nullptr);

    // join: attn needs both CSR and projections
    cudaStreamWaitEvent(0, ev_join, 0);
    attn_kernel<<<(n * 32 + 255) / 256, 256>>>();
    gemm128<1><<<dim3((n + 127) / 128, 1), 256, GEMM_SMEM>>>(nullptr, n, ba, h, skip, (float*)d_out);
}

// round 7
// speedup vs baseline: 1.4675x; 1.1935x over previous
#include <cuda_runtime.h>
#include <cuda_fp16.h>
#include <cuda_bf16.h>
#include <mma.h>
#include <stdint.h>
#include <math.h>

using namespace nvcuda;

#define N_NODES 100000
#define E_EDGES 1600000
#define DD 128
#define SCAN_BS 512
#define NB ((N_NODES + SCAN_BS - 1) / SCAN_BS)   // 196

// ---------------- scratch (device globals; no allocations) ----------------
__device__ float          g_q [N_NODES * DD];      // [N][128] fp32, rel_pri/sqrt_dk folded in
__device__ __half         g_kv[N_NODES * 2 * DD];  // [N][256]: k' (128) then v' (128)
__device__ float          g_t [N_NODES * DD];      // aggregated messages
__device__ __nv_bfloat16  g_Wbhi[3 * 128 * 128];   // composed projection weights bf16 hi, [j][k]
__device__ __nv_bfloat16  g_Wblo[3 * 128 * 128];
__device__ __nv_bfloat16  g_Wahi[128 * 128];       // output weights bf16 hi, [j][k]
__device__ __nv_bfloat16  g_Walo[128 * 128];
__device__ float          g_beff[384];
__device__ int            g_cnt     [N_NODES];
__device__ int            g_rowstart[N_NODES];
__device__ int            g_cursor  [N_NODES];
__device__ int            g_csr_src [E_EDGES];
__device__ int            g_bsums   [256];

// ---------------- zero the histogram ----------------
__global__ void zero_cnt_kernel() {
    int i = blockIdx.x * blockDim.x + threadIdx.x;
    if (i < N_NODES) g_cnt[i] = 0;
}

// ---------------- compose weights -> plain [j][k] bf16 hi/lo ----------------
__global__ void build_weights(const float* __restrict__ Wk, const float* __restrict__ Wq,
                              const float* __restrict__ Wv, const float* __restrict__ Wa,
                              const float* __restrict__ rel_att, const float* __restrict__ rel_msg,
                              const float* __restrict__ rel_pri) {
    int idx = blockIdx.x * blockDim.x + threadIdx.x;   // 512*128 = 65536 threads
    int j = idx >> 7;        // 0..511
    int k = idx & 127;
    float val;
    if (j < 128) {
        val = Wq[j * DD + k] * rel_pri[j >> 4] * 0.25f;    // rel_pri[h]/sqrt(DK)
    } else if (j < 384) {
        int jj = (j - 128) & 127;
        const float* W = (j < 256) ? Wk : Wv;
        const float* R = (j < 256) ? rel_att : rel_msg;
        int hh = jj >> 4, e = jj & 15;
        float s = 0.f;
#pragma unroll
        for (int d2 = 0; d2 < 16; d2++)
            s += W[(hh * 16 + d2) * DD + k] * R[hh * 256 + d2 * 16 + e];
        val = s;
    } else {
        val = Wa[(j - 384) * DD + k];
    }
    __nv_bfloat16 hi = __float2bfloat16(val);
    __nv_bfloat16 lo = __float2bfloat16(val - __bfloat162float(hi));
    if (j < 384) {
        g_Wbhi[j * 128 + k] = hi;
        g_Wblo[j * 128 + k] = lo;
    } else {
        g_Wahi[(j - 384) * 128 + k] = hi;
        g_Walo[(j - 384) * 128 + k] = lo;
    }
}

__global__ void build_bias(const float* __restrict__ bk, const float* __restrict__ bq,
                           const float* __restrict__ bv,
                           const float* __restrict__ rel_att, const float* __restrict__ rel_msg,
                           const float* __restrict__ rel_pri) {
    int j = threadIdx.x;   // 384 threads
    if (j >= 384) return;
    float val;
    if (j < 128) {
        val = bq[j] * rel_pri[j >> 4] * 0.25f;
    } else {
        int jj = (j - 128) & 127;
        const float* b = (j < 256) ? bk : bv;
        const float* R = (j < 256) ? rel_att : rel_msg;
        int hh = jj >> 4, e = jj & 15;
        float s = 0.f;
#pragma unroll
        for (int d2 = 0; d2 < 16; d2++)
            s += b[hh * 16 + d2] * R[hh * 256 + d2 * 16 + e];
        val = s;
    }
    g_beff[j] = val;
}

// ---------------- CSR build ----------------
__global__ void hist_kernel(const int* __restrict__ dst, int E) {
    int e = blockIdx.x * blockDim.x + threadIdx.x;
    if (e < E) atomicAdd(&g_cnt[dst[e]], 1);
}

__global__ void scan1_kernel() {
    __shared__ int sdata[SCAN_BS];
    int tid = threadIdx.x;
    int i = blockIdx.x * SCAN_BS + tid;
    int v = (i < N_NODES) ? g_cnt[i] : 0;
    sdata[tid] = v;
    __syncthreads();
#pragma unroll
    for (int off = 1; off < SCAN_BS; off <<= 1) {
        int x = (tid >= off) ? sdata[tid - off] : 0;
        __syncthreads();
        sdata[tid] += x;
        __syncthreads();
    }
    if (i < N_NODES) g_rowstart[i] = sdata[tid] - v;
    if (tid == SCAN_BS - 1) g_bsums[blockIdx.x] = sdata[tid];
}

__global__ void scan2_kernel() {
    __shared__ int sdata[256];
    int tid = threadIdx.x;
    int v = (tid < NB) ? g_bsums[tid] : 0;
    sdata[tid] = v;
    __syncthreads();
#pragma unroll
    for (int off = 1; off < 256; off <<= 1) {
        int x = (tid >= off) ? sdata[tid - off] : 0;
        __syncthreads();
        sdata[tid] += x;
        __syncthreads();
    }
    g_bsums[tid] = sdata[tid] - v;
}

__global__ void scan3_kernel() {
    int i = blockIdx.x * SCAN_BS + threadIdx.x;
    if (i < N_NODES) {
        int r = g_rowstart[i] + g_bsums[i >> 9];
        g_rowstart[i] = r;
        g_cursor[i] = r;
    }
}

__global__ void scatter_kernel(const int* __restrict__ src, const int* __restrict__ dst, int E) {
    int e = blockIdx.x * blockDim.x + threadIdx.x;
    if (e < E) {
        int p = atomicAdd(&g_cursor[dst[e]], 1);
        g_csr_src[p] = src[e];
    }
}

// ---------------- wmma GEMM: C[128, NT*128] = A[128,128] @ W^T, bf16x3 split ----------------
// MODE 0: A = h, W = g_Wbhi/lo (3 n-tiles in-block loop), +bias -> g_q fp32 / g_kv fp16
// MODE 1: A = g_t, W = g_Wahi/lo, out = alpha*(acc+ba) + (1-alpha)*h
#define ALD 136                               // bf16 leading dim (272B rows: conflict-free, 16B aligned)
#define CLD 132                               // f32 C leading dim
#define SM_AHI 0
#define SM_ALO (128 * ALD * 2)                // 34816
#define SM_BHI (2 * 128 * ALD * 2)            // 69632
#define SM_BLO (SM_BHI + 128 * ALD * 2)
#define SM_C   SM_BHI                         // C tile aliases B (B reloaded per nt)
#define TC_SMEM (4 * 128 * ALD * 2)           // 139264

template <int MODE>
__global__ void __launch_bounds__(256, 1)
tc_gemm(const float* __restrict__ Ain, int nrows,
        const float* __restrict__ ba, const float* __restrict__ haux,
        const float* __restrict__ skip, float* __restrict__ outp) {
    constexpr int NT = (MODE == 0) ? 3 : 1;
    extern __shared__ char smem[];
    __nv_bfloat16* Ah = (__nv_bfloat16*)(smem + SM_AHI);
    __nv_bfloat16* Al = (__nv_bfloat16*)(smem + SM_ALO);
    __nv_bfloat16* Bh = (__nv_bfloat16*)(smem + SM_BHI);
    __nv_bfloat16* Bl = (__nv_bfloat16*)(smem + SM_BLO);
    float*         Cs = (float*)(smem + SM_C);

    const int tid = threadIdx.x;
    const int wid = tid >> 5;
    const int m0 = blockIdx.x * 128;
    const int warp_m = wid & 3;        // 4 warps over M (32 rows each)
    const int warp_n = wid >> 2;       // 2 warps over N (64 cols each)

    // ---- load A tile (fp32 -> bf16 hi/lo) ----
    {
        const float* Ap = (MODE == 0) ? Ain : g_t;
        int row = tid >> 1;
        int c0 = (tid & 1) << 6;
        bool vrow = (m0 + row) < nrows;
        const float* arow = Ap + (size_t)(m0 + row) * DD + c0;
        __nv_bfloat16* ah = Ah + row * ALD + c0;
        __nv_bfloat16* al = Al + row * ALD + c0;
#pragma unroll
        for (int cc = 0; cc < 16; cc++) {
            float4 v = vrow ? *(const float4*)(arow + cc * 4) : make_float4(0.f, 0.f, 0.f, 0.f);
            __nv_bfloat16 h0 = __float2bfloat16(v.x), h1 = __float2bfloat16(v.y);
            __nv_bfloat16 h2 = __float2bfloat16(v.z), h3 = __float2bfloat16(v.w);
            __nv_bfloat162 ph0; ph0.x = h0; ph0.y = h1;
            __nv_bfloat162 ph1; ph1.x = h2; ph1.y = h3;
            __nv_bfloat16 l0 = __float2bfloat16(v.x - __bfloat162float(h0));
            __nv_bfloat16 l1 = __float2bfloat16(v.y - __bfloat162float(h1));
            __nv_bfloat16 l2 = __float2bfloat16(v.z - __bfloat162float(h2));
            __nv_bfloat16 l3 = __float2bfloat16(v.w - __bfloat162float(h3));
            __nv_bfloat162 pl0; pl0.x = l0; pl0.y = l1;
            __nv_bfloat162 pl1; pl1.x = l2; pl1.y = l3;
            uint2 uh = make_uint2(*(unsigned*)&ph0, *(unsigned*)&ph1);
            uint2 ul = make_uint2(*(unsigned*)&pl0, *(unsigned*)&pl1);
            *(uint2*)(ah + cc * 4) = uh;
            *(uint2*)(al + cc * 4) = ul;
        }
    }

    float alpha = 0.f, beta = 0.f;
    if (MODE == 1) {
        float s = __ldg(skip);
        alpha = 1.f / (1.f + __expf(-s));
        beta = 1.f - alpha;
    }

    for (int nt = 0; nt < NT; nt++) {
        // ---- load B n-tile (bf16 hi/lo, [j][k] -> smem ld=ALD); also covers A-ready sync ----
        __syncthreads();
        {
            const uint4* sh = (const uint4*)((MODE == 0) ? (g_Wbhi + nt * 16384) : g_Wahi);
            const uint4* sl = (const uint4*)((MODE == 0) ? (g_Wblo + nt * 16384) : g_Walo);
#pragma unroll
            for (int i = 0; i < 8; i++) {
                int u = tid + i * 256;        // 0..2047
                int j = u >> 4, q = u & 15;   // row j, 16B chunk q (row = 256B = 16 chunks)
                *(uint4*)((char*)Bh + j * (ALD * 2) + q * 16) = sh[u];
                *(uint4*)((char*)Bl + j * (ALD * 2) + q * 16) = sl[u];
            }
        }
        __syncthreads();

        // ---- wmma mainloop: acc = Ah*Bh + Ah*Bl + Al*Bh ----
        wmma::fragment<wmma::accumulator, 16, 16, 16, float> acc[2][4];
#pragma unroll
        for (int i = 0; i < 2; i++)
#pragma unroll
            for (int j = 0; j < 4; j++) wmma::fill_fragment(acc[i][j], 0.f);

#pragma unroll
        for (int ks = 0; ks < 8; ks++) {
            const int kk = ks * 16;
            wmma::fragment<wmma::matrix_a, 16, 16, 16, __nv_bfloat16, wmma::row_major> ah[2], al[2];
#pragma unroll
            for (int i = 0; i < 2; i++) {
                const __nv_bfloat16* ap = Ah + (warp_m * 32 + i * 16) * ALD + kk;
                const __nv_bfloat16* lp = Al + (warp_m * 32 + i * 16) * ALD + kk;
                wmma::load_matrix_sync(ah[i], ap, ALD);
                wmma::load_matrix_sync(al[i], lp, ALD);
            }
            wmma::fragment<wmma::matrix_b, 16, 16, 16, __nv_bfloat16, wmma::col_major> bh[4], bl[4];
#pragma unroll
            for (int j = 0; j < 4; j++) {
                const __nv_bfloat16* bp = Bh + (warp_n * 64 + j * 16) * ALD + kk;
                const __nv_bfloat16* lp = Bl + (warp_n * 64 + j * 16) * ALD + kk;
                wmma::load_matrix_sync(bh[j], bp, ALD);
                wmma::load_matrix_sync(bl[j], lp, ALD);
            }
#pragma unroll
            for (int i = 0; i < 2; i++)
#pragma unroll
                for (int j = 0; j < 4; j++) {
                    wmma::mma_sync(acc[i][j], ah[i], bh[j], acc[i][j]);
                    wmma::mma_sync(acc[i][j], ah[i], bl[j], acc[i][j]);
                    wmma::mma_sync(acc[i][j], al[i], bh[j], acc[i][j]);
                }
        }

        // ---- stage accumulators to C smem (aliases B; all mma reads of B are done) ----
        __syncthreads();
#pragma unroll
        for (int i = 0; i < 2; i++)
#pragma unroll
            for (int j = 0; j < 4; j++)
                wmma::store_matrix_sync(Cs + (warp_m * 32 + i * 16) * CLD + warp_n * 64 + j * 16,
                                        acc[i][j], CLD, wmma::mem_row_major);
        __syncthreads();

        // ---- epilogue: coalesced writes from C smem ----
        {
            int row = tid >> 1;
            int c0 = (tid & 1) << 6;
            int grow = m0 + row;
            if (grow < nrows) {
                const float* crow = Cs + row * CLD + c0;
                const int jb = nt * 128 + c0;
                if (MODE == 0) {
                    if (nt == 0) {
                        float* dst = g_q + (size_t)grow * DD + c0;
#pragma unroll
                        for (int cc = 0; cc < 16; cc++) {
                            float4 o = *(const float4*)(crow + cc * 4);
                            o.x += g_beff[jb + cc * 4];
                            o.y += g_beff[jb + cc * 4 + 1];
                            o.z += g_beff[jb + cc * 4 + 2];
                            o.w += g_beff[jb + cc * 4 + 3];
                            *(float4*)(dst + cc * 4) = o;
                        }
                    } else {
                        __half* dst = g_kv + (size_t)grow * 256 + (nt - 1) * 128 + c0;
#pragma unroll
                        for (int cc = 0; cc < 8; cc++) {
                            uint4 u;
                            unsigned* up = &u.x;
#pragma unroll
                            for (int p = 0; p < 4; p++) {
                                int c = cc * 8 + p * 2;
                                float f0 = crow[c]     + g_beff[jb + c];
                                float f1 = crow[c + 1] + g_beff[jb + c + 1];
                                __half2 hh = __floats2half2_rn(f0, f1);
                                up[p] = *(unsigned*)&hh;
                            }
                            *(uint4*)(dst + cc * 8) = u;
                        }
                    }
                } else {
                    float* dst = outp + (size_t)grow * DD + c0;
                    const float* hrow = haux + (size_t)grow * DD + c0;
#pragma unroll
                    for (int cc = 0; cc < 16; cc++) {
                        float4 hv = *(const float4*)(hrow + cc * 4);
                        float4 o;
                        o.x = alpha * (crow[cc * 4]     + ba[c0 + cc * 4])     + beta * hv.x;
                        o.y = alpha * (crow[cc * 4 + 1] + ba[c0 + cc * 4 + 1]) + beta * hv.y;
                        o.z = alpha * (crow[cc * 4 + 2] + ba[c0 + cc * 4 + 2]) + beta * hv.z;
                        o.w = alpha * (crow[cc * 4 + 3] + ba[c0 + cc * 4 + 3]) + beta * hv.w;
                        *(float4*)(dst + cc * 4) = o;
                    }
                }
            }
        }
    }
}

// ---------------- fused edge softmax + aggregation: one warp per dst node ----------------
__global__ void attn_kernel() {
    int w = (blockIdx.x * blockDim.x + threadIdx.x) >> 5;
    int t = threadIdx.x & 31;
    if (w >= N_NODES) return;
    const int d = w;

    float4 q4 = *(const float4*)(g_q + d * DD + t * 4);
    int start = g_rowstart[d];
    int cnt = g_cnt[d];

    float4 acc = make_float4(0.f, 0.f, 0.f, 0.f);
    float den = 0.f;
    const int* __restrict__ cs = g_csr_src + start;

    int i = 0;
    for (; i + 2 <= cnt; i += 2) {
        int s0 = cs[i];
        int s1 = cs[i + 1];
        const uint2* __restrict__ r0 = reinterpret_cast<const uint2*>(g_kv + s0 * 2 * DD);
        const uint2* __restrict__ r1 = reinterpret_cast<const uint2*>(g_kv + s1 * 2 * DD);
        uint2 ku0 = r0[t];
        uint2 vu0 = r0[32 + t];
        uint2 ku1 = r1[t];
        uint2 vu1 = r1[32 + t];

        float2 k01 = __half22float2(*reinterpret_cast<__half2*>(&ku0.x));
        float2 k23 = __half22float2(*reinterpret_cast<__half2*>(&ku0.y));
        float p0 = q4.x * k01.x + q4.y * k01.y + q4.z * k23.x + q4.w * k23.y;
        float2 m01 = __half22float2(*reinterpret_cast<__half2*>(&ku1.x));
        float2 m23 = __half22float2(*reinterpret_cast<__half2*>(&ku1.y));
        float p1 = q4.x * m01.x + q4.y * m01.y + q4.z * m23.x + q4.w * m23.y;

        p0 += __shfl_xor_sync(0xffffffffu, p0, 1);
        p1 += __shfl_xor_sync(0xffffffffu, p1, 1);
        p0 += __shfl_xor_sync(0xffffffffu, p0, 2);
        p1 += __shfl_xor_sync(0xffffffffu, p1, 2);
        float ex0 = __expf(p0);
        float ex1 = __expf(p1);

        float2 v01 = __half22float2(*reinterpret_cast<__half2*>(&vu0.x));
        float2 v23 = __half22float2(*reinterpret_cast<__half2*>(&vu0.y));
        float2 w01 = __half22float2(*reinterpret_cast<__half2*>(&vu1.x));
        float2 w23 = __half22float2(*reinterpret_cast<__half2*>(&vu1.y));
        den += ex0 + ex1;
        acc.x += ex0 * v01.x + ex1 * w01.x;
        acc.y += ex0 * v01.y + ex1 * w01.y;
        acc.z += ex0 * v23.x + ex1 * w23.x;
        acc.w += ex0 * v23.y + ex1 * w23.y;
    }
    if (i < cnt) {
        int s0 = cs[i];
        const uint2* __restrict__ r0 = reinterpret_cast<const uint2*>(g_kv + s0 * 2 * DD);
        uint2 ku0 = r0[t];
        uint2 vu0 = r0[32 + t];
        float2 k01 = __half22float2(*reinterpret_cast<__half2*>(&ku0.x));
        float2 k23 = __half22float2(*reinterpret_cast<__half2*>(&ku0.y));
        float p0 = q4.x * k01.x + q4.y * k01.y + q4.z * k23.x + q4.w * k23.y;
        p0 += __shfl_xor_sync(0xffffffffu, p0, 1);
        p0 += __shfl_xor_sync(0xffffffffu, p0, 2);
        float ex0 = __expf(p0);
        float2 v01 = __half22float2(*reinterpret_cast<__half2*>(&vu0.x));
        float2 v23 = __half22float2(*reinterpret_cast<__half2*>(&vu0.y));
        den += ex0;
        acc.x += ex0 * v01.x;
        acc.y += ex0 * v01.y;
        acc.z += ex0 * v23.x;
        acc.w += ex0 * v23.y;
    }
    float inv = (cnt > 0) ? (1.f / den) : 0.f;
    float4 o = make_float4(acc.x * inv, acc.y * inv, acc.z * inv, acc.w * inv);
    *(float4*)(g_t + d * DD + t * 4) = o;
}

// ---------------- launch: CSR chain forked onto a side stream ----------------
extern "C" void kernel_launch(void* const* d_in, const int* in_sizes, int n_in,
                              void* d_out, int out_size) {
    const float* h       = (const float*)d_in[0];
    const int*   src     = (const int*)d_in[1];
    const int*   dst     = (const int*)d_in[2];
    const float* Wk      = (const float*)d_in[3];
    const float* bk      = (const float*)d_in[4];
    const float* Wq      = (const float*)d_in[5];
    const float* bq      = (const float*)d_in[6];
    const float* Wv      = (const float*)d_in[7];
    const float* bv      = (const float*)d_in[8];
    const float* Wa      = (const float*)d_in[9];
    const float* ba      = (const float*)d_in[10];
    const float* rel_att = (const float*)d_in[11];
    const float* rel_msg = (const float*)d_in[12];
    const float* rel_pri = (const float*)d_in[13];
    const float* skip    = (const float*)d_in[14];

    const int n = in_sizes[0] / DD;   // 100000
    const int E = in_sizes[1];        // 1600000
    const int ntiles = (n + 127) / 128;

    static cudaStream_t s2 = nullptr;
    static cudaEvent_t ev_fork = nullptr, ev_join = nullptr;
    static bool attr_done = false;
    if (!s2) {
        cudaStreamCreateWithFlags(&s2, cudaStreamNonBlocking);
        cudaEventCreateWithFlags(&ev_fork, cudaEventDisableTiming);
        cudaEventCreateWithFlags(&ev_join, cudaEventDisableTiming);
    }
    if (!attr_done) {
        cudaFuncSetAttribute(tc_gemm<0>, cudaFuncAttributeMaxDynamicSharedMemorySize, TC_SMEM);
        cudaFuncSetAttribute(tc_gemm<1>, cudaFuncAttributeMaxDynamicSharedMemorySize, TC_SMEM);
        attr_done = true;
    }

    // fork: CSR chain on s2
    cudaEventRecord(ev_fork, 0);
    cudaStreamWaitEvent(s2, ev_fork, 0);

    zero_cnt_kernel<<<(N_NODES + 255) / 256, 256, 0, s2>>>();
    hist_kernel<<<(E + 255) / 256, 256, 0, s2>>>(dst, E);
    scan1_kernel<<<NB, SCAN_BS, 0, s2>>>();
    scan2_kernel<<<1, 256, 0, s2>>>();
    scan3_kernel<<<NB, SCAN_BS, 0, s2>>>();
    scatter_kernel<<<(E + 255) / 256, 256, 0, s2>>>(src, dst, E);
    cudaEventRecord(ev_join, s2);

    // projection chain on main stream
    build_weights<<<256, 256>>>(Wk, Wq, Wv, Wa, rel_att, rel_msg, rel_pri);
    build_bias<<<1, 384>>>(bk, bq, bv, rel_att, rel_msg, rel_pri);
    tc_gemm<0><<<ntiles, 256, TC_SMEM>>>(h, n, nullptr, nullptr, nullptr, nullptr);

    // join: attn needs both CSR and projections
    cudaStreamWaitEvent(0, ev_join, 0);
    attn_kernel<<<(n * 32 + 255) / 256, 256>>>();
    tc_gemm<1><<<ntiles, 256, TC_SMEM>>>(nullptr, n, ba, h, skip, (float*)d_out);
}